// round 15
// baseline (speedup 1.0000x reference)
#include <cuda_runtime.h>
#include <cuda_fp16.h>
#include <math.h>
#include <cstdint>

// ---------------------------------------------------------------------------
// MSMDDeformRegionAttn  (N=4, Lq=300, C=256, H=8, Dh=32, L=4, P=4, ROI=7)
//
//   1. value = input_flatten @ Wv + bv            (79788 x 256 x 256)  HMMA
//   2. ROI-align 7x7 -> roi planes (fp16 split, precomputed offsets)
//   3. pw partials = roi_flat @ [Wp | Ww]         (1200 x 12544 x 384) HMMA
//   4. k_sample: fused reduce + tanh/softmax + deformable gather
//   5. out = att @ Wo + bo                        (1200 x 256 x 256)   HMMA
//
// GEMM core: 128x128 block, 4 warps, 64x64 warp tile (MMA:LDSM = 6:1),
// mma.sync m16n8k16 fp16 with 2-way fp16 split (3 cross-products).
// Weights pre-scaled x64 (epilogue x 1/64).
// ---------------------------------------------------------------------------

#define NBATCH  4
#define LQ      300
#define NQ      (NBATCH * LQ)      // 1200
#define CDIM    256
#define NHEADS  8
#define DH      32
#define NLVL    4
#define NPTS    4
#define ROI     7
#define LEN_IN  19947
#define ROI_DIM (ROI * ROI * CDIM) // 12544
#define NPW     384                // 256 (Wp) + 128 (Ww)
#define SPLITK  28
#define KCHUNK  (ROI_DIM / SPLITK) // 448 = 14 * 32
#define MV      (NBATCH * LEN_IN)  // 79788
#define NQPAD   1280               // 10 * 128
#define WSCALE  64.0f
#define WSCALE_INV (1.0f / 64.0f)

// ------------------------- scratch (static device mem) ---------------------
__device__ float  g_value[(size_t)MV * CDIM];                  // 81.7 MB
__device__ __half g_roiA[(size_t)2 * NQPAD * ROI_DIM];         // 64.2 MB
__device__ __half g_attA[(size_t)2 * NQPAD * CDIM];            //  1.3 MB
__device__ float  g_part[(size_t)SPLITK * NQ * NPW];           // 51.6 MB
__device__ __half g_btv[(size_t)2 * CDIM * CDIM];
__device__ __half g_btpw[(size_t)2 * NPW * ROI_DIM];           // 19.3 MB
__device__ __half g_btwo[(size_t)2 * CDIM * CDIM];

// --------------------------- PTX primitives --------------------------------
__device__ __forceinline__ uint32_t smem_u32(const void* p)
{
    uint32_t a;
    asm("{ .reg .u64 t; cvta.to.shared.u64 t, %1; cvt.u32.u64 %0, t; }"
        : "=r"(a) : "l"(p));
    return a;
}
__device__ __forceinline__ void cp16(uint32_t dst, const void* src)
{
    asm volatile("cp.async.cg.shared.global [%0], [%1], 16;"
                 :: "r"(dst), "l"(src));
}
__device__ __forceinline__ void mma_f16(float* d, const uint32_t* a,
                                        const uint32_t* b)
{
    asm volatile(
        "mma.sync.aligned.m16n8k16.row.col.f32.f16.f16.f32 "
        "{%0,%1,%2,%3}, {%4,%5,%6,%7}, {%8,%9}, {%0,%1,%2,%3};"
        : "+f"(d[0]), "+f"(d[1]), "+f"(d[2]), "+f"(d[3])
        : "r"(a[0]), "r"(a[1]), "r"(a[2]), "r"(a[3]), "r"(b[0]), "r"(b[1]));
}
__device__ __forceinline__ void ldsm4(uint32_t* r, uint32_t addr)
{
    asm volatile(
        "ldmatrix.sync.aligned.m8n8.x4.shared.b16 {%0,%1,%2,%3}, [%4];"
        : "=r"(r[0]), "=r"(r[1]), "=r"(r[2]), "=r"(r[3]) : "r"(addr));
}

// --------------------------- fp16 2-way split -------------------------------
__device__ __forceinline__ void h2split(float x, __half& h0, __half& h1)
{
    h0 = __float2half_rn(x);
    h1 = __float2half_rn(x - __half2float(h0));
}

// ===== MMA compute core: 128x128 block, 4 warps (2x2), 64x64 warp tile =====
// A planes at sb+aBase (+8192 for plane1), B planes at sb+bBase (+8192).
// Swizzled rows: 32 fp16 (64B) per row, 16B chunk c -> c ^ ((r>>1)&3).
// Per k16: B 8 ldsm4 (2 planes x 4), A 8 ldsm4, 96 MMA (3 products x 4i x 8j).
#define MMA_STEP(aBase, bBase)                                                 \
    do {                                                                       \
        _Pragma("unroll")                                                      \
        for (int h = 0; h < 2; h++) {                                          \
            uint32_t bfr[2][8][2];                                             \
            _Pragma("unroll")                                                  \
            for (int pb = 0; pb < 2; pb++)                                     \
                _Pragma("unroll")                                              \
                for (int jj = 0; jj < 4; jj++) {                               \
                    uint32_t r[4];                                             \
                    ldsm4(r, sb + (bBase) + pb * 8192 + bOff + jj * 1024 +     \
                             ((((uint32_t)(h * 2) + bCk) ^ bSwz) << 4));       \
                    bfr[pb][jj * 2][0] = r[0]; bfr[pb][jj * 2][1] = r[1];      \
                    bfr[pb][jj * 2 + 1][0] = r[2];                             \
                    bfr[pb][jj * 2 + 1][1] = r[3];                             \
                }                                                              \
            _Pragma("unroll")                                                  \
            for (int pa = 0; pa < 2; pa++) {                                   \
                uint32_t af[4][4];                                             \
                _Pragma("unroll")                                              \
                for (int i = 0; i < 4; i++)                                    \
                    ldsm4(af[i], sb + (aBase) + pa * 8192 + aOff + i * 1024 +  \
                                 ((((uint32_t)(h * 2) + aCk) ^ aSwz) << 4));   \
                const int npb = 2 - pa;                                        \
                for (int pb = 0; pb < npb; pb++)                               \
                    _Pragma("unroll")                                          \
                    for (int i = 0; i < 4; i++)                                \
                        _Pragma("unroll")                                      \
                        for (int j = 0; j < 8; j++)                            \
                            mma_f16(acc[i][j], af[i], bfr[pb][j]);             \
            }                                                                  \
        }                                                                      \
    } while (0)

#define MMA_EPILOGUE()                                                         \
    do {                                                                       \
        const int colBase = n0 + warp_n * 64 + (lane & 3) * 2;                 \
        const int rowBase = m0 + warp_m * 64 + (lane >> 2);                    \
        _Pragma("unroll")                                                      \
        for (int i = 0; i < 4; i++) {                                          \
            _Pragma("unroll")                                                  \
            for (int j = 0; j < 8; j++) {                                      \
                const int gc = colBase + j * 8;                                \
                float bx = 0.f, by = 0.f;                                      \
                if (bias) { bx = bias[gc]; by = bias[gc + 1]; }                \
                const int r0 = rowBase + i * 16;                               \
                if (r0 < M) {                                                  \
                    float2 v = make_float2(acc[i][j][0] * outScale + bx,       \
                                           acc[i][j][1] * outScale + by);      \
                    *(float2*)(C + (size_t)r0 * ldc + gc) = v;                 \
                }                                                              \
                const int r1 = r0 + 8;                                         \
                if (r1 < M) {                                                  \
                    float2 v = make_float2(acc[i][j][2] * outScale + bx,       \
                                           acc[i][j][3] * outScale + by);      \
                    *(float2*)(C + (size_t)r1 * ldc + gc) = v;                 \
                }                                                              \
            }                                                                  \
        }                                                                      \
    } while (0)

#define MMA_LDSM_COORDS()                                                      \
    const uint32_t aRow = (uint32_t)(warp_m * 64 + (lane & 15));               \
    const uint32_t aOff = aRow * 64;                                           \
    const uint32_t aSwz = (aRow >> 1) & 3;                                     \
    const uint32_t aCk = (uint32_t)(lane >> 4);                                \
    const uint32_t bRow =                                                      \
        (uint32_t)(warp_n * 64 + ((lane >> 4) << 3) + (lane & 7));             \
    const uint32_t bOff = bRow * 64;                                           \
    const uint32_t bSwz = (bRow >> 1) & 3;                                     \
    const uint32_t bCk = (uint32_t)((lane >> 3) & 1)

#define SMEM_TOT 65536

// ------------- fp16x2 HMMA GEMM, A already split (pw / out GEMMs) ----------
__global__ __launch_bounds__(128, 2) void mma_gemm(
    const __half* __restrict__ Ap, size_t aPlane, int lda,
    const __half* __restrict__ Bp, size_t bPlane, int ldb,
    float* __restrict__ C, int ldc, long long cSplitStride,
    int M, int kChunkTot, const float* __restrict__ bias, float outScale)
{
    extern __shared__ __align__(16) char smc[];
    const uint32_t sb = smem_u32(smc);
    const int tid = threadIdx.x, lane = tid & 31, wid = tid >> 5;
    const int warp_m = wid >> 1, warp_n = wid & 1;
    const int m0 = blockIdx.y * 128, n0 = blockIdx.x * 128;
    const int kBase = blockIdx.z * kChunkTot;
    C += (long long)blockIdx.z * cSplitStride;

    // cp.async coords: thread t -> rows lr, lr+32, lr+64, lr+96; chunk lc
    const int lr = tid >> 2, lc = tid & 3;
    const uint32_t swz = (uint32_t)(lc ^ ((lr >> 1) & 3)) << 4;
    const uint32_t d1 = (uint32_t)lr * 64 + swz;
    const __half* aS = Ap + (size_t)(m0 + lr) * lda + kBase + lc * 8;
    const __half* bS = Bp + (size_t)(n0 + lr) * ldb + kBase + lc * 8;

#define ISSUE(bo, ke)                                                          \
    do {                                                                       \
        _Pragma("unroll")                                                      \
        for (int g = 0; g < 4; g++) {                                          \
            const uint32_t dd = d1 + (uint32_t)g * 2048u;                      \
            cp16(sb + (bo) + dd, aS + (size_t)(g * 32) * lda + (ke));          \
            cp16(sb + (bo) + 8192 + dd,                                        \
                 aS + aPlane + (size_t)(g * 32) * lda + (ke));                 \
            cp16(sb + (bo) + 16384 + dd, bS + (size_t)(g * 32) * ldb + (ke));  \
            cp16(sb + (bo) + 24576 + dd,                                       \
                 bS + bPlane + (size_t)(g * 32) * ldb + (ke));                 \
        }                                                                      \
        asm volatile("cp.async.commit_group;" ::: "memory");                   \
    } while (0)

    MMA_LDSM_COORDS();

    float acc[4][8][4];
#pragma unroll
    for (int i = 0; i < 4; i++)
#pragma unroll
        for (int j = 0; j < 8; j++)
#pragma unroll
            for (int e = 0; e < 4; e++) acc[i][j][e] = 0.f;

    const int nIter = kChunkTot / 32;
    ISSUE(0u, 0);
    uint32_t bo = 0;
    for (int it = 0; it < nIter; it++) {
        asm volatile("cp.async.wait_group 0;" ::: "memory");
        __syncthreads();
        if (it + 1 < nIter) ISSUE(bo ^ 32768u, (it + 1) * 32);
        MMA_STEP(bo, bo + 16384);
        bo ^= 32768u;
    }
#undef ISSUE

    MMA_EPILOGUE();
}

// ------- fp16x2 HMMA GEMM, A fp32 with in-kernel split (value GEMM) --------
__global__ __launch_bounds__(128, 2) void mma_gemm_f32(
    const float* __restrict__ A, int lda,
    const __half* __restrict__ Bp, size_t bPlane, int ldb,
    float* __restrict__ C, int ldc,
    int M, int kChunkTot, const float* __restrict__ bias, float outScale)
{
    extern __shared__ __align__(16) char smc[];
    const uint32_t sb = smem_u32(smc);
    const int tid = threadIdx.x, lane = tid & 31, wid = tid >> 5;
    const int warp_m = wid >> 1, warp_n = wid & 1;
    const int m0 = blockIdx.y * 128, n0 = blockIdx.x * 128;

    // A: thread t owns full row t (32 fp32 per k32 step)
    const int row = tid;
    const bool aval = (m0 + row) < M;
    const float* aRowP = A + (size_t)(m0 + row) * lda;
    const uint32_t sw = ((uint32_t)row >> 1) & 3;
    uint32_t aoffc[4];
#pragma unroll
    for (int c = 0; c < 4; c++)
        aoffc[c] = (uint32_t)row * 64 + (((uint32_t)c ^ sw) << 4);

    // B cp.async coords
    const int lr = tid >> 2, lc = tid & 3;
    const uint32_t swz = (uint32_t)(lc ^ ((lr >> 1) & 3)) << 4;
    const uint32_t d1 = (uint32_t)lr * 64 + swz;
    const __half* bS = Bp + (size_t)(n0 + lr) * ldb + lc * 8;

#define ISSUEB(bo, ke)                                                         \
    do {                                                                       \
        _Pragma("unroll")                                                      \
        for (int g = 0; g < 4; g++) {                                          \
            const uint32_t dd = d1 + (uint32_t)g * 2048u;                      \
            cp16(sb + (bo) + dd, bS + (size_t)(g * 32) * ldb + (ke));          \
            cp16(sb + (bo) + 8192 + dd,                                        \
                 bS + bPlane + (size_t)(g * 32) * ldb + (ke));                 \
        }                                                                      \
        asm volatile("cp.async.commit_group;" ::: "memory");                   \
    } while (0)

    MMA_LDSM_COORDS();

    float acc[4][8][4];
#pragma unroll
    for (int i = 0; i < 4; i++)
#pragma unroll
        for (int j = 0; j < 8; j++)
#pragma unroll
            for (int e = 0; e < 4; e++) acc[i][j][e] = 0.f;

    const int nIter = kChunkTot / 32;

    float fa[32];
#pragma unroll
    for (int j = 0; j < 8; j++) {
        float4 v = aval ? *(const float4*)(aRowP + j * 4)
                        : make_float4(0.f, 0.f, 0.f, 0.f);
        fa[j * 4 + 0] = v.x; fa[j * 4 + 1] = v.y;
        fa[j * 4 + 2] = v.z; fa[j * 4 + 3] = v.w;
    }
    ISSUEB(32768u, 0);

    for (int it = 0; it < nIter; it++) {
        // split + STS into A buffer it&1 (layout identical to pre-split path)
        {
            const uint32_t aBase = (uint32_t)(it & 1) * 16384u;
            unsigned short h0[32], h1[32];
#pragma unroll
            for (int e = 0; e < 32; e++) {
                __half a0, a1;
                h2split(fa[e], a0, a1);
                h0[e] = __half_as_ushort(a0);
                h1[e] = __half_as_ushort(a1);
            }
#pragma unroll
            for (int c = 0; c < 4; c++) {
                uint4 q;
                q.x = (uint32_t)h0[c*8+0] | ((uint32_t)h0[c*8+1] << 16);
                q.y = (uint32_t)h0[c*8+2] | ((uint32_t)h0[c*8+3] << 16);
                q.z = (uint32_t)h0[c*8+4] | ((uint32_t)h0[c*8+5] << 16);
                q.w = (uint32_t)h0[c*8+6] | ((uint32_t)h0[c*8+7] << 16);
                *(uint4*)(smc + aBase + aoffc[c]) = q;
                q.x = (uint32_t)h1[c*8+0] | ((uint32_t)h1[c*8+1] << 16);
                q.y = (uint32_t)h1[c*8+2] | ((uint32_t)h1[c*8+3] << 16);
                q.z = (uint32_t)h1[c*8+4] | ((uint32_t)h1[c*8+5] << 16);
                q.w = (uint32_t)h1[c*8+6] | ((uint32_t)h1[c*8+7] << 16);
                *(uint4*)(smc + aBase + 8192 + aoffc[c]) = q;
            }
        }
        if (it + 1 < nIter) {
#pragma unroll
            for (int j = 0; j < 8; j++) {
                float4 v = aval
                    ? *(const float4*)(aRowP + (it + 1) * 32 + j * 4)
                    : make_float4(0.f, 0.f, 0.f, 0.f);
                fa[j * 4 + 0] = v.x; fa[j * 4 + 1] = v.y;
                fa[j * 4 + 2] = v.z; fa[j * 4 + 3] = v.w;
            }
        }
        asm volatile("cp.async.wait_group 0;" ::: "memory");
        __syncthreads();
        if (it + 1 < nIter)
            ISSUEB(32768u + (uint32_t)((it + 1) & 1) * 16384u, (it + 1) * 32);

        const uint32_t aBase = (uint32_t)(it & 1) * 16384u;
        const uint32_t bBase = 32768u + (uint32_t)(it & 1) * 16384u;
        MMA_STEP(aBase, bBase);
    }
#undef ISSUEB

    MMA_EPILOGUE();
}

// -------------- weight transpose + scale(x64) + fp16 2-way split ------------
__global__ __launch_bounds__(256) void k_tsplit2(
    const float* __restrict__ W0, __half* __restrict__ o0,
    const float* __restrict__ W1, __half* __restrict__ o1)
{
    __shared__ float t[32][33];
    const float* W = blockIdx.z ? W1 : W0;
    __half* out = blockIdx.z ? o1 : o0;
    const size_t plane = (size_t)CDIM * CDIM;
    const int kb = blockIdx.y * 32, nb = blockIdx.x * 32;
    const int c = threadIdx.x & 31, r8 = threadIdx.x >> 5;
#pragma unroll
    for (int i = 0; i < 4; i++)
        t[r8 + i * 8][c] = W[(size_t)(kb + r8 + i * 8) * CDIM + nb + c];
    __syncthreads();
#pragma unroll
    for (int i = 0; i < 4; i++) {
        const int n = nb + r8 + i * 8;
        const int k = kb + c;
        float x = t[c][r8 + i * 8] * WSCALE;
        __half h0, h1;
        h2split(x, h0, h1);
        size_t o = (size_t)n * CDIM + k;
        out[o] = h0;
        out[plane + o] = h1;
    }
}

__global__ __launch_bounds__(256) void k_tsplit_pw(
    const float* __restrict__ Wp, const float* __restrict__ Ww,
    __half* __restrict__ out)
{
    __shared__ float t[32][33];
    const size_t plane = (size_t)NPW * ROI_DIM;
    const bool isW = blockIdx.x >= 8;
    const float* W = isW ? Ww : Wp;
    const int N = isW ? 128 : 256;
    const int rowOff = isW ? 256 : 0;
    const int nb = (isW ? (blockIdx.x - 8) : blockIdx.x) * 32;
    const int kb = blockIdx.y * 32;
    const int c = threadIdx.x & 31, r8 = threadIdx.x >> 5;
#pragma unroll
    for (int i = 0; i < 4; i++)
        t[r8 + i * 8][c] = W[(size_t)(kb + r8 + i * 8) * N + nb + c];
    __syncthreads();
#pragma unroll
    for (int i = 0; i < 4; i++) {
        const int n = nb + r8 + i * 8;
        const int k = kb + c;
        float x = t[c][r8 + i * 8] * WSCALE;
        __half h0, h1;
        h2split(x, h0, h1);
        size_t o = (size_t)(n + rowOff) * ROI_DIM + k;
        out[o] = h0;
        out[plane + o] = h1;
    }
}

// ------------------- ROI align -> split fp16 planes -------------------------
__global__ __launch_bounds__(512) void k_roi(const float* __restrict__ ref,
                                             const float* __restrict__ value,
                                             __half* __restrict__ roiA)
{
    const int q = blockIdx.x;
    const int n = q / LQ;
    const int tx = threadIdx.x;        // 0..63 -> channels tx*4..tx*4+3
    const int ty = threadIdx.y;        // 0..7  -> positions ty, ty+8, ...
    const int tid = ty * 64 + tx;

    __shared__ int4  s_off[ROI * ROI];
    __shared__ float4 s_wt[ROI * ROI];

    if (tid < ROI * ROI) {
        const float4 rp = *(const float4*)(ref + (size_t)q * 16);
        const float x1 = (rp.x - 0.5f * rp.z) * 150.f - 0.5f;
        const float y1 = (rp.y - 0.5f * rp.w) * 100.f - 0.5f;
        const float bw = rp.z * 150.f / (float)ROI;
        const float bh = rp.w * 100.f / (float)ROI;
        const int by = tid / ROI, bx = tid % ROI;
        const float y = y1 + bh * ((float)by + 0.5f);
        const float x = x1 + bw * ((float)bx + 0.5f);
        const float fy = floorf(y), fx = floorf(x);
        const int y0 = (int)fy, x0 = (int)fx;
        const float wy1 = y - fy, wx1 = x - fx;
        const float wy0 = 1.f - wy1, wx0 = 1.f - wx1;
        const bool ya = (y0 >= 0) && (y0 < 100);
        const bool yb = (y0 + 1 >= 0) && (y0 + 1 < 100);
        const bool xa = (x0 >= 0) && (x0 < 150);
        const bool xb = (x0 + 1 >= 0) && (x0 + 1 < 150);
        const int yc0 = min(max(y0, 0), 99);
        const int yc1 = min(max(y0 + 1, 0), 99);
        const int xc0 = min(max(x0, 0), 149);
        const int xc1 = min(max(x0 + 1, 0), 149);
        s_off[tid] = make_int4((yc0 * 150 + xc0) * CDIM,
                               (yc0 * 150 + xc1) * CDIM,
                               (yc1 * 150 + xc0) * CDIM,
                               (yc1 * 150 + xc1) * CDIM);
        s_wt[tid] = make_float4((ya && xa) ? wy0 * wx0 : 0.f,
                                (ya && xb) ? wy0 * wx1 : 0.f,
                                (yb && xa) ? wy1 * wx0 : 0.f,
                                (yb && xb) ? wy1 * wx1 : 0.f);
    }
    __syncthreads();

    const float* base = value + (size_t)n * LEN_IN * CDIM + tx * 4;
    __half* out0 = roiA + (size_t)q * ROI_DIM + tx * 4;
    __half* out1 = out0 + (size_t)NQPAD * ROI_DIM;

#pragma unroll
    for (int pos = ty; pos < ROI * ROI; pos += 8) {
        const int4 off = s_off[pos];
        const float4 wt = s_wt[pos];
        const float4 v00 = *(const float4*)(base + off.x);
        const float4 v01 = *(const float4*)(base + off.y);
        const float4 v10 = *(const float4*)(base + off.z);
        const float4 v11 = *(const float4*)(base + off.w);

        float o[4];
        o[0] = v00.x * wt.x + v01.x * wt.y + v10.x * wt.z + v11.x * wt.w;
        o[1] = v00.y * wt.x + v01.y * wt.y + v10.y * wt.z + v11.y * wt.w;
        o[2] = v00.z * wt.x + v01.z * wt.y + v10.z * wt.z + v11.z * wt.w;
        o[3] = v00.w * wt.x + v01.w * wt.y + v10.w * wt.z + v11.w * wt.w;

        unsigned short p0[4], p1[4];
#pragma unroll
        for (int e = 0; e < 4; e++) {
            __half a0, a1;
            h2split(o[e], a0, a1);
            p0[e] = __half_as_ushort(a0);
            p1[e] = __half_as_ushort(a1);
        }
        uint2 q0 = make_uint2((uint32_t)p0[0] | ((uint32_t)p0[1] << 16),
                              (uint32_t)p0[2] | ((uint32_t)p0[3] << 16));
        uint2 q1 = make_uint2((uint32_t)p1[0] | ((uint32_t)p1[1] << 16),
                              (uint32_t)p1[2] | ((uint32_t)p1[3] << 16));
        *(uint2*)(out0 + (size_t)pos * CDIM) = q0;
        *(uint2*)(out1 + (size_t)pos * CDIM) = q1;
    }
}

// ---- fused: split-K reduce + bias + tanh/softmax + deformable sampling ----
__global__ __launch_bounds__(256) void k_sample(const float* __restrict__ ref,
                                                const float* __restrict__ part,
                                                const float* __restrict__ bp,
                                                const float* __restrict__ bw,
                                                const float* __restrict__ value,
                                                __half* __restrict__ attA)
{
    int q = blockIdx.x;
    int n = q / LQ;
    int t = threadIdx.x;
    int h = t >> 5, d = t & 31;
    __shared__ float s_pw[NPW];
    __shared__ float s_w[NHEADS][16];
    __shared__ float s_ref[16];
    __shared__ int4  s_goff[NHEADS][16];
    __shared__ float4 s_gw[NHEADS][16];

    for (int j = t; j < NPW; j += 256) {
        float s = (j < 256) ? bp[j] : bw[j - 256];
        const float* p = part + (size_t)q * NPW + j;
#pragma unroll
        for (int z = 0; z < SPLITK; z++)
            s += p[(size_t)z * NQ * NPW];
        s_pw[j] = s;
    }
    if (t < 16) s_ref[t] = ref[(size_t)q * 16 + t];
    __syncthreads();

    if (t < 128) {
        const int HL[4] = {100, 50, 25, 13};
        const int WL[4] = {150, 75, 38, 19};
        const int SL[4] = {0, 15000, 18750, 19700};
        int hh = t >> 4, lp = t & 15, l = lp >> 2;
        float ox = tanhf(s_pw[2 * t]);
        float oy = tanhf(s_pw[2 * t + 1]);
        float pxn = s_ref[l * 4 + 0] + ox * s_ref[l * 4 + 2] * 0.5f;
        float pyn = s_ref[l * 4 + 1] + oy * s_ref[l * 4 + 3] * 0.5f;
        s_w[hh][lp] = s_pw[256 + t];

        float px = pxn * (float)WL[l] - 0.5f;
        float py = pyn * (float)HL[l] - 0.5f;
        float fy = floorf(py), fx = floorf(px);
        int y0 = (int)fy, x0 = (int)fx;
        float wy1 = py - fy, wx1 = px - fx;
        float wy0 = 1.f - wy1, wx0 = 1.f - wx1;
        bool ya = (y0 >= 0) && (y0 < HL[l]);
        bool yb = (y0 + 1 >= 0) && (y0 + 1 < HL[l]);
        bool xa = (x0 >= 0) && (x0 < WL[l]);
        bool xb = (x0 + 1 >= 0) && (x0 + 1 < WL[l]);
        int yc0 = min(max(y0, 0), HL[l] - 1);
        int yc1 = min(max(y0 + 1, 0), HL[l] - 1);
        int xc0 = min(max(x0, 0), WL[l] - 1);
        int xc1 = min(max(x0 + 1, 0), WL[l] - 1);
        int baseOff = (n * LEN_IN + SL[l]) * CDIM + hh * DH;
        s_goff[hh][lp] = make_int4(baseOff + (yc0 * WL[l] + xc0) * CDIM,
                                   baseOff + (yc0 * WL[l] + xc1) * CDIM,
                                   baseOff + (yc1 * WL[l] + xc0) * CDIM,
                                   baseOff + (yc1 * WL[l] + xc1) * CDIM);
        s_gw[hh][lp] = make_float4((ya && xa) ? wy0 * wx0 : 0.f,
                                   (ya && xb) ? wy0 * wx1 : 0.f,
                                   (yb && xa) ? wy1 * wx0 : 0.f,
                                   (yb && xb) ? wy1 * wx1 : 0.f);
    }
    __syncthreads();
    if (t < NHEADS) {
        float mx = -1e30f;
#pragma unroll
        for (int i = 0; i < 16; i++) mx = fmaxf(mx, s_w[t][i]);
        float sum = 0.f;
#pragma unroll
        for (int i = 0; i < 16; i++) {
            float e = expf(s_w[t][i] - mx);
            s_w[t][i] = e;
            sum += e;
        }
        float inv = 1.f / sum;
#pragma unroll
        for (int i = 0; i < 16; i++) s_w[t][i] *= inv;
    }
    __syncthreads();

    float acc = 0.f;
#pragma unroll
    for (int lp = 0; lp < 16; lp++) {
        const int4 off = s_goff[h][lp];
        const float4 gw = s_gw[h][lp];
        float v00 = value[off.x + d];
        float v01 = value[off.y + d];
        float v10 = value[off.z + d];
        float v11 = value[off.w + d];
        float inner = v00 * gw.x + v01 * gw.y + v10 * gw.z + v11 * gw.w;
        acc += s_w[h][lp] * inner;
    }
    __half h0, h1;
    h2split(acc, h0, h1);
    attA[(size_t)q * CDIM + t] = h0;
    attA[(size_t)NQPAD * CDIM + (size_t)q * CDIM + t] = h1;
}

// ------------------------------ launcher -----------------------------------
extern "C" void kernel_launch(void* const* d_in, const int* in_sizes, int n_in,
                              void* d_out, int out_size)
{
    (void)in_sizes; (void)n_in; (void)out_size;
    const float* ref  = (const float*)d_in[1];
    const float* flat = (const float*)d_in[2];
    const float* Wv   = (const float*)d_in[6];
    const float* bv   = (const float*)d_in[7];
    const float* Wp   = (const float*)d_in[8];
    const float* bp   = (const float*)d_in[9];
    const float* Ww   = (const float*)d_in[10];
    const float* bw   = (const float*)d_in[11];
    const float* Wo   = (const float*)d_in[12];
    const float* bo   = (const float*)d_in[13];
    float* out = (float*)d_out;

    float *p_value, *p_part;
    __half *p_roiA, *p_attA, *p_btv, *p_btpw, *p_btwo;
    cudaGetSymbolAddress((void**)&p_value, g_value);
    cudaGetSymbolAddress((void**)&p_roiA,  g_roiA);
    cudaGetSymbolAddress((void**)&p_attA,  g_attA);
    cudaGetSymbolAddress((void**)&p_part,  g_part);
    cudaGetSymbolAddress((void**)&p_btv,   g_btv);
    cudaGetSymbolAddress((void**)&p_btpw,  g_btpw);
    cudaGetSymbolAddress((void**)&p_btwo,  g_btwo);

    cudaFuncSetAttribute(mma_gemm, cudaFuncAttributeMaxDynamicSharedMemorySize,
                         SMEM_TOT);
    cudaFuncSetAttribute(mma_gemm_f32,
                         cudaFuncAttributeMaxDynamicSharedMemorySize, SMEM_TOT);

    // 0. weight transpose + x64 scale + fp16 split
    k_tsplit2<<<dim3(CDIM / 32, CDIM / 32, 2), 256>>>(Wv, p_btv, Wo, p_btwo);
    k_tsplit_pw<<<dim3(12, ROI_DIM / 32), 256>>>(Wp, Ww, p_btpw);

    // 1. value = input_flatten @ Wv + bv  (A split fused; grid 2 x 624)
    mma_gemm_f32<<<dim3(CDIM / 128, (MV + 127) / 128, 1), 128, SMEM_TOT>>>(
        flat, CDIM,
        p_btv, (size_t)CDIM * CDIM, CDIM,
        p_value, CDIM, MV, CDIM, bv, WSCALE_INV);

    // 2. ROI align -> split fp16 roi planes
    k_roi<<<NQ, dim3(64, 8)>>>(ref, p_value, p_roiA);

    // 3. pw partials: roi @ [Wp | Ww]  (grid 3 x 10 x 28)
    mma_gemm<<<dim3(NPW / 128, NQPAD / 128, SPLITK), 128, SMEM_TOT>>>(
        p_roiA, (size_t)NQPAD * ROI_DIM, ROI_DIM,
        p_btpw, (size_t)NPW * ROI_DIM, ROI_DIM,
        p_part, NPW, (long long)NQ * NPW, NQ, KCHUNK, nullptr, WSCALE_INV);

    // 4. fused reduce + deformable sampling -> split fp16 att planes
    k_sample<<<NQ, 256>>>(ref, p_part, bp, bw, p_value, p_attA);

    // 5. out = att @ Wo + bo  (grid 2 x 10)
    mma_gemm<<<dim3(CDIM / 128, NQPAD / 128, 1), 128, SMEM_TOT>>>(
        p_attA, (size_t)NQPAD * CDIM, CDIM,
        p_btwo, (size_t)CDIM * CDIM, CDIM,
        out, CDIM, 0, NQ, CDIM, bo, WSCALE_INV);
}

// round 17
// speedup vs baseline: 1.0758x; 1.0758x over previous
#include <cuda_runtime.h>
#include <cuda_fp16.h>
#include <math.h>
#include <cstdint>

// ---------------------------------------------------------------------------
// MSMDDeformRegionAttn  (N=4, Lq=300, C=256, H=8, Dh=32, L=4, P=4, ROI=7)
//
//   1. value = input_flatten @ Wv + bv            (79788 x 256 x 256)  HMMA
//      (A-operand fp32 -> fp16x2 split fused into the GEMM A-load)
//   2. ROI-align 7x7 -> roi planes (fp16 split, precomputed offsets)
//   3. pw partials = roi_flat @ [Wp | Ww]         (1200 x 12544 x 384) HMMA
//   4. k_sample: fused reduce + tanh/softmax + deformable gather
//   5. out = att @ Wo + bo                        (1200 x 256 x 256)   HMMA
//
// GEMM core (frozen): 128x128 block, 8 warps (2x4), 64x32 warp tile,
// 2-stage cp.async; mma.sync m16n8k16 fp16 with 2-way fp16 split of each
// fp32 operand (3 cross-products) -> residual ~2^-22. Weights pre-scaled
// x64 (epilogue x 1/64) to keep residuals in fp16 normal range.
// ---------------------------------------------------------------------------

#define NBATCH  4
#define LQ      300
#define NQ      (NBATCH * LQ)      // 1200
#define CDIM    256
#define NHEADS  8
#define DH      32
#define NLVL    4
#define NPTS    4
#define ROI     7
#define LEN_IN  19947
#define ROI_DIM (ROI * ROI * CDIM) // 12544
#define NPW     384                // 256 (Wp) + 128 (Ww)
#define SPLITK  28
#define KCHUNK  (ROI_DIM / SPLITK) // 448 = 14 * 32
#define MV      (NBATCH * LEN_IN)  // 79788
#define NQPAD   1280               // 10 * 128
#define WSCALE  64.0f
#define WSCALE_INV (1.0f / 64.0f)

// ------------------------- scratch (static device mem) ---------------------
__device__ float  g_value[(size_t)MV * CDIM];                  // 81.7 MB
__device__ __half g_roiA[(size_t)2 * NQPAD * ROI_DIM];         // 64.2 MB
__device__ __half g_attA[(size_t)2 * NQPAD * CDIM];            //  1.3 MB
__device__ float  g_part[(size_t)SPLITK * NQ * NPW];           // 51.6 MB
__device__ __half g_btv[(size_t)2 * CDIM * CDIM];
__device__ __half g_btpw[(size_t)2 * NPW * ROI_DIM];           // 19.3 MB
__device__ __half g_btwo[(size_t)2 * CDIM * CDIM];

// --------------------------- PTX primitives --------------------------------
__device__ __forceinline__ uint32_t smem_u32(const void* p)
{
    uint32_t a;
    asm("{ .reg .u64 t; cvta.to.shared.u64 t, %1; cvt.u32.u64 %0, t; }"
        : "=r"(a) : "l"(p));
    return a;
}
__device__ __forceinline__ void cp16(uint32_t dst, const void* src)
{
    asm volatile("cp.async.cg.shared.global [%0], [%1], 16;"
                 :: "r"(dst), "l"(src));
}
__device__ __forceinline__ void mma_f16(float* d, const uint32_t* a,
                                        const uint32_t* b)
{
    asm volatile(
        "mma.sync.aligned.m16n8k16.row.col.f32.f16.f16.f32 "
        "{%0,%1,%2,%3}, {%4,%5,%6,%7}, {%8,%9}, {%0,%1,%2,%3};"
        : "+f"(d[0]), "+f"(d[1]), "+f"(d[2]), "+f"(d[3])
        : "r"(a[0]), "r"(a[1]), "r"(a[2]), "r"(a[3]), "r"(b[0]), "r"(b[1]));
}
__device__ __forceinline__ void ldsm4(uint32_t* r, uint32_t addr)
{
    asm volatile(
        "ldmatrix.sync.aligned.m8n8.x4.shared.b16 {%0,%1,%2,%3}, [%4];"
        : "=r"(r[0]), "=r"(r[1]), "=r"(r[2]), "=r"(r[3]) : "r"(addr));
}

// --------------------------- fp16 2-way split -------------------------------
__device__ __forceinline__ void h2split(float x, __half& h0, __half& h1)
{
    h0 = __float2half_rn(x);
    h1 = __float2half_rn(x - __half2float(h0));
}

// ===== shared MMA compute core (128x128 tile, 8 warps 2x4, one k32 step) ====
#define MMA_STEP(aBase, bBase)                                                 \
    do {                                                                       \
        _Pragma("unroll")                                                      \
        for (int h = 0; h < 2; h++) {                                          \
            uint32_t bfr[2][4][2];                                             \
            _Pragma("unroll")                                                  \
            for (int pb = 0; pb < 2; pb++)                                     \
                _Pragma("unroll")                                              \
                for (int jj = 0; jj < 2; jj++) {                               \
                    uint32_t r[4];                                             \
                    ldsm4(r, sb + (bBase) + pb * 8192 + bOff + jj * 1024 +     \
                             ((((uint32_t)(h * 2) + bCk) ^ bSwz) << 4));       \
                    bfr[pb][jj * 2][0] = r[0]; bfr[pb][jj * 2][1] = r[1];      \
                    bfr[pb][jj * 2 + 1][0] = r[2];                             \
                    bfr[pb][jj * 2 + 1][1] = r[3];                             \
                }                                                              \
            _Pragma("unroll")                                                  \
            for (int pa = 0; pa < 2; pa++) {                                   \
                uint32_t af[4][4];                                             \
                _Pragma("unroll")                                              \
                for (int i = 0; i < 4; i++)                                    \
                    ldsm4(af[i], sb + (aBase) + pa * 8192 + aOff + i * 1024 +  \
                                 ((((uint32_t)(h * 2) + aCk) ^ aSwz) << 4));   \
                const int npb = 2 - pa;                                        \
                for (int pb = 0; pb < npb; pb++)                               \
                    _Pragma("unroll")                                          \
                    for (int i = 0; i < 4; i++)                                \
                        _Pragma("unroll")                                      \
                        for (int j = 0; j < 4; j++)                            \
                            mma_f16(acc[i][j], af[i], bfr[pb][j]);             \
            }                                                                  \
        }                                                                      \
    } while (0)

#define MMA_EPILOGUE()                                                         \
    do {                                                                       \
        const int colBase = n0 + warp_n * 32 + (lane & 3) * 2;                 \
        const int rowBase = m0 + warp_m * 64 + (lane >> 2);                    \
        _Pragma("unroll")                                                      \
        for (int i = 0; i < 4; i++) {                                          \
            _Pragma("unroll")                                                  \
            for (int j = 0; j < 4; j++) {                                      \
                const int gc = colBase + j * 8;                                \
                float bx = 0.f, by = 0.f;                                      \
                if (bias) { bx = bias[gc]; by = bias[gc + 1]; }                \
                const int r0 = rowBase + i * 16;                               \
                if (r0 < M) {                                                  \
                    float2 v = make_float2(acc[i][j][0] * outScale + bx,       \
                                           acc[i][j][1] * outScale + by);      \
                    *(float2*)(C + (size_t)r0 * ldc + gc) = v;                 \
                }                                                              \
                const int r1 = r0 + 8;                                         \
                if (r1 < M) {                                                  \
                    float2 v = make_float2(acc[i][j][2] * outScale + bx,       \
                                           acc[i][j][3] * outScale + by);      \
                    *(float2*)(C + (size_t)r1 * ldc + gc) = v;                 \
                }                                                              \
            }                                                                  \
        }                                                                      \
    } while (0)

#define MMA_LDSM_COORDS()                                                      \
    const uint32_t aRow = (uint32_t)(warp_m * 64 + (lane & 15));               \
    const uint32_t aOff = aRow * 64;                                           \
    const uint32_t aSwz = (aRow >> 1) & 3;                                     \
    const uint32_t aCk = (uint32_t)(lane >> 4);                                \
    const uint32_t bRow =                                                      \
        (uint32_t)(warp_n * 32 + ((lane >> 4) << 3) + (lane & 7));             \
    const uint32_t bOff = bRow * 64;                                           \
    const uint32_t bSwz = (bRow >> 1) & 3;                                     \
    const uint32_t bCk = (uint32_t)((lane >> 3) & 1)

#define SMEM_TOT 65536

// ------------- fp16x2 HMMA GEMM, A already split (pw / out GEMMs) ----------
__global__ __launch_bounds__(256, 2) void mma_gemm(
    const __half* __restrict__ Ap, size_t aPlane, int lda,
    const __half* __restrict__ Bp, size_t bPlane, int ldb,
    float* __restrict__ C, int ldc, long long cSplitStride,
    int M, int kChunkTot, const float* __restrict__ bias, float outScale)
{
    extern __shared__ __align__(16) char smc[];
    const uint32_t sb = smem_u32(smc);
    const int tid = threadIdx.x, lane = tid & 31, wid = tid >> 5;
    const int warp_m = wid >> 2, warp_n = wid & 3;
    const int m0 = blockIdx.y * 128, n0 = blockIdx.x * 128;
    const int kBase = blockIdx.z * kChunkTot;
    C += (long long)blockIdx.z * cSplitStride;

    const int lr = tid >> 2, lc = tid & 3;
    const uint32_t swz = (uint32_t)(lc ^ ((lr >> 1) & 3)) << 4;
    const uint32_t d1 = (uint32_t)lr * 64 + swz;
    const uint32_t d2 = d1 + 64 * 64;
    const __half* aS = Ap + (size_t)(m0 + lr) * lda + kBase + lc * 8;
    const __half* bS = Bp + (size_t)(n0 + lr) * ldb + kBase + lc * 8;

#define ISSUE(bo, ke)                                                          \
    do {                                                                       \
        cp16(sb + (bo) + d1, aS + (ke));                                       \
        cp16(sb + (bo) + 8192 + d1, aS + aPlane + (ke));                       \
        cp16(sb + (bo) + d2, aS + (size_t)64 * lda + (ke));                    \
        cp16(sb + (bo) + 8192 + d2, aS + aPlane + (size_t)64 * lda + (ke));    \
        cp16(sb + (bo) + 16384 + d1, bS + (ke));                               \
        cp16(sb + (bo) + 24576 + d1, bS + bPlane + (ke));                      \
        cp16(sb + (bo) + 16384 + d2, bS + (size_t)64 * ldb + (ke));            \
        cp16(sb + (bo) + 24576 + d2, bS + bPlane + (size_t)64 * ldb + (ke));   \
        asm volatile("cp.async.commit_group;" ::: "memory");                   \
    } while (0)

    MMA_LDSM_COORDS();

    float acc[4][4][4];
#pragma unroll
    for (int i = 0; i < 4; i++)
#pragma unroll
        for (int j = 0; j < 4; j++)
#pragma unroll
            for (int e = 0; e < 4; e++) acc[i][j][e] = 0.f;

    const int nIter = kChunkTot / 32;
    ISSUE(0u, 0);
    uint32_t bo = 0;
    for (int it = 0; it < nIter; it++) {
        asm volatile("cp.async.wait_group 0;" ::: "memory");
        __syncthreads();
        if (it + 1 < nIter) ISSUE(bo ^ 32768u, (it + 1) * 32);
        MMA_STEP(bo, bo + 16384);
        bo ^= 32768u;
    }
#undef ISSUE

    MMA_EPILOGUE();
}

// ------- fp16x2 HMMA GEMM, A fp32 with in-kernel split (value GEMM) --------
__global__ __launch_bounds__(256, 2) void mma_gemm_f32(
    const float* __restrict__ A, int lda,
    const __half* __restrict__ Bp, size_t bPlane, int ldb,
    float* __restrict__ C, int ldc,
    int M, int kChunkTot, const float* __restrict__ bias, float outScale)
{
    extern __shared__ __align__(16) char smc[];
    const uint32_t sb = smem_u32(smc);
    const int tid = threadIdx.x, lane = tid & 31, wid = tid >> 5;
    const int warp_m = wid >> 2, warp_n = wid & 3;
    const int m0 = blockIdx.y * 128, n0 = blockIdx.x * 128;

    const int row = tid >> 1;
    const int kh = (tid & 1) * 16;
    const bool aval = (m0 + row) < M;
    const float* aRowP = A + (size_t)(m0 + row) * lda + kh;
    const uint32_t sw = ((uint32_t)row >> 1) & 3;
    const uint32_t c0 = (uint32_t)(tid & 1) * 2;
    const uint32_t aoff0 = (uint32_t)row * 64 + ((c0 ^ sw) << 4);
    const uint32_t aoff1 = (uint32_t)row * 64 + (((c0 + 1) ^ sw) << 4);

    const int lr = tid >> 2, lc = tid & 3;
    const uint32_t swz = (uint32_t)(lc ^ ((lr >> 1) & 3)) << 4;
    const uint32_t d1 = (uint32_t)lr * 64 + swz;
    const uint32_t d2 = d1 + 64 * 64;
    const __half* bS = Bp + (size_t)(n0 + lr) * ldb + lc * 8;

#define ISSUEB(bo, ke)                                                         \
    do {                                                                       \
        cp16(sb + (bo) + d1, bS + (ke));                                       \
        cp16(sb + (bo) + 8192 + d1, bS + bPlane + (ke));                       \
        cp16(sb + (bo) + d2, bS + (size_t)64 * ldb + (ke));                    \
        cp16(sb + (bo) + 8192 + d2, bS + bPlane + (size_t)64 * ldb + (ke));    \
        asm volatile("cp.async.commit_group;" ::: "memory");                   \
    } while (0)

    MMA_LDSM_COORDS();

    float acc[4][4][4];
#pragma unroll
    for (int i = 0; i < 4; i++)
#pragma unroll
        for (int j = 0; j < 4; j++)
#pragma unroll
            for (int e = 0; e < 4; e++) acc[i][j][e] = 0.f;

    const int nIter = kChunkTot / 32;

    float fa[16];
#pragma unroll
    for (int j = 0; j < 4; j++) {
        float4 v = aval ? *(const float4*)(aRowP + j * 4)
                        : make_float4(0.f, 0.f, 0.f, 0.f);
        fa[j * 4 + 0] = v.x; fa[j * 4 + 1] = v.y;
        fa[j * 4 + 2] = v.z; fa[j * 4 + 3] = v.w;
    }
    ISSUEB(32768u, 0);

    for (int it = 0; it < nIter; it++) {
        {
            const uint32_t aBase = (uint32_t)(it & 1) * 16384u;
            unsigned short h0[16], h1[16];
#pragma unroll
            for (int e = 0; e < 16; e++) {
                __half a0, a1;
                h2split(fa[e], a0, a1);
                h0[e] = __half_as_ushort(a0);
                h1[e] = __half_as_ushort(a1);
            }
            uint4 q;
            q.x = (uint32_t)h0[0] | ((uint32_t)h0[1] << 16);
            q.y = (uint32_t)h0[2] | ((uint32_t)h0[3] << 16);
            q.z = (uint32_t)h0[4] | ((uint32_t)h0[5] << 16);
            q.w = (uint32_t)h0[6] | ((uint32_t)h0[7] << 16);
            *(uint4*)(smc + aBase + aoff0) = q;
            q.x = (uint32_t)h0[8] | ((uint32_t)h0[9] << 16);
            q.y = (uint32_t)h0[10] | ((uint32_t)h0[11] << 16);
            q.z = (uint32_t)h0[12] | ((uint32_t)h0[13] << 16);
            q.w = (uint32_t)h0[14] | ((uint32_t)h0[15] << 16);
            *(uint4*)(smc + aBase + aoff1) = q;
            q.x = (uint32_t)h1[0] | ((uint32_t)h1[1] << 16);
            q.y = (uint32_t)h1[2] | ((uint32_t)h1[3] << 16);
            q.z = (uint32_t)h1[4] | ((uint32_t)h1[5] << 16);
            q.w = (uint32_t)h1[6] | ((uint32_t)h1[7] << 16);
            *(uint4*)(smc + aBase + 8192 + aoff0) = q;
            q.x = (uint32_t)h1[8] | ((uint32_t)h1[9] << 16);
            q.y = (uint32_t)h1[10] | ((uint32_t)h1[11] << 16);
            q.z = (uint32_t)h1[12] | ((uint32_t)h1[13] << 16);
            q.w = (uint32_t)h1[14] | ((uint32_t)h1[15] << 16);
            *(uint4*)(smc + aBase + 8192 + aoff1) = q;
        }
        if (it + 1 < nIter) {
#pragma unroll
            for (int j = 0; j < 4; j++) {
                float4 v = aval
                    ? *(const float4*)(aRowP + (it + 1) * 32 + j * 4)
                    : make_float4(0.f, 0.f, 0.f, 0.f);
                fa[j * 4 + 0] = v.x; fa[j * 4 + 1] = v.y;
                fa[j * 4 + 2] = v.z; fa[j * 4 + 3] = v.w;
            }
        }
        asm volatile("cp.async.wait_group 0;" ::: "memory");
        __syncthreads();
        if (it + 1 < nIter)
            ISSUEB(32768u + (uint32_t)((it + 1) & 1) * 16384u, (it + 1) * 32);

        const uint32_t aBase = (uint32_t)(it & 1) * 16384u;
        const uint32_t bBase = 32768u + (uint32_t)(it & 1) * 16384u;
        MMA_STEP(aBase, bBase);
    }
#undef ISSUEB

    MMA_EPILOGUE();
}

// ------ all weight transposes + scale(x64) + fp16 2-way split, one launch ---
// z=0: Wp (bx<8) / Ww (bx>=8) into btpw  (grid 12 x 392)
// z=1: Wv (by<8) / Wo (8<=by<16) into btv/btwo; other blocks exit.
__global__ __launch_bounds__(256) void k_tsplit_all(
    const float* __restrict__ Wp, const float* __restrict__ Ww,
    __half* __restrict__ btpw,
    const float* __restrict__ Wv, __half* __restrict__ btv,
    const float* __restrict__ Wo, __half* __restrict__ btwo)
{
    __shared__ float t[32][33];
    const int c = threadIdx.x & 31, r8 = threadIdx.x >> 5;

    const float* W;
    __half* out;
    size_t plane;
    int N, K, rowOff, nb, kb;

    if (blockIdx.z == 0) {
        const bool isW = blockIdx.x >= 8;
        W = isW ? Ww : Wp;
        out = btpw;
        plane = (size_t)NPW * ROI_DIM;
        N = isW ? 128 : 256;
        K = ROI_DIM;
        rowOff = isW ? 256 : 0;
        nb = (isW ? ((int)blockIdx.x - 8) : (int)blockIdx.x) * 32;
        kb = blockIdx.y * 32;
    } else {
        if (blockIdx.x >= 8 || blockIdx.y >= 16) return;
        const bool isO = blockIdx.y >= 8;
        W = isO ? Wo : Wv;
        out = isO ? btwo : btv;
        plane = (size_t)CDIM * CDIM;
        N = CDIM;
        K = CDIM;
        rowOff = 0;
        nb = blockIdx.x * 32;
        kb = (isO ? ((int)blockIdx.y - 8) : (int)blockIdx.y) * 32;
    }

#pragma unroll
    for (int i = 0; i < 4; i++)
        t[r8 + i * 8][c] = W[(size_t)(kb + r8 + i * 8) * N + nb + c];
    __syncthreads();
#pragma unroll
    for (int i = 0; i < 4; i++) {
        const int n = nb + r8 + i * 8;
        const int k = kb + c;
        float x = t[c][r8 + i * 8] * WSCALE;
        __half h0, h1;
        h2split(x, h0, h1);
        size_t o = (size_t)(n + rowOff) * K + k;
        out[o] = h0;
        out[plane + o] = h1;
    }
}

// ------------------- ROI align -> split fp16 planes -------------------------
__global__ __launch_bounds__(512) void k_roi(const float* __restrict__ ref,
                                             const float* __restrict__ value,
                                             __half* __restrict__ roiA)
{
    const int q = blockIdx.x;
    const int n = q / LQ;
    const int tx = threadIdx.x;        // 0..63 -> channels tx*4..tx*4+3
    const int ty = threadIdx.y;        // 0..7  -> positions ty, ty+8, ...
    const int tid = ty * 64 + tx;

    __shared__ int4  s_off[ROI * ROI];
    __shared__ float4 s_wt[ROI * ROI];

    if (tid < ROI * ROI) {
        const float4 rp = *(const float4*)(ref + (size_t)q * 16);
        const float x1 = (rp.x - 0.5f * rp.z) * 150.f - 0.5f;
        const float y1 = (rp.y - 0.5f * rp.w) * 100.f - 0.5f;
        const float bw = rp.z * 150.f / (float)ROI;
        const float bh = rp.w * 100.f / (float)ROI;
        const int by = tid / ROI, bx = tid % ROI;
        const float y = y1 + bh * ((float)by + 0.5f);
        const float x = x1 + bw * ((float)bx + 0.5f);
        const float fy = floorf(y), fx = floorf(x);
        const int y0 = (int)fy, x0 = (int)fx;
        const float wy1 = y - fy, wx1 = x - fx;
        const float wy0 = 1.f - wy1, wx0 = 1.f - wx1;
        const bool ya = (y0 >= 0) && (y0 < 100);
        const bool yb = (y0 + 1 >= 0) && (y0 + 1 < 100);
        const bool xa = (x0 >= 0) && (x0 < 150);
        const bool xb = (x0 + 1 >= 0) && (x0 + 1 < 150);
        const int yc0 = min(max(y0, 0), 99);
        const int yc1 = min(max(y0 + 1, 0), 99);
        const int xc0 = min(max(x0, 0), 149);
        const int xc1 = min(max(x0 + 1, 0), 149);
        s_off[tid] = make_int4((yc0 * 150 + xc0) * CDIM,
                               (yc0 * 150 + xc1) * CDIM,
                               (yc1 * 150 + xc0) * CDIM,
                               (yc1 * 150 + xc1) * CDIM);
        s_wt[tid] = make_float4((ya && xa) ? wy0 * wx0 : 0.f,
                                (ya && xb) ? wy0 * wx1 : 0.f,
                                (yb && xa) ? wy1 * wx0 : 0.f,
                                (yb && xb) ? wy1 * wx1 : 0.f);
    }
    __syncthreads();

    const float* base = value + (size_t)n * LEN_IN * CDIM + tx * 4;
    __half* out0 = roiA + (size_t)q * ROI_DIM + tx * 4;
    __half* out1 = out0 + (size_t)NQPAD * ROI_DIM;

#pragma unroll
    for (int pos = ty; pos < ROI * ROI; pos += 8) {
        const int4 off = s_off[pos];
        const float4 wt = s_wt[pos];
        const float4 v00 = *(const float4*)(base + off.x);
        const float4 v01 = *(const float4*)(base + off.y);
        const float4 v10 = *(const float4*)(base + off.z);
        const float4 v11 = *(const float4*)(base + off.w);

        float o[4];
        o[0] = v00.x * wt.x + v01.x * wt.y + v10.x * wt.z + v11.x * wt.w;
        o[1] = v00.y * wt.x + v01.y * wt.y + v10.y * wt.z + v11.y * wt.w;
        o[2] = v00.z * wt.x + v01.z * wt.y + v10.z * wt.z + v11.z * wt.w;
        o[3] = v00.w * wt.x + v01.w * wt.y + v10.w * wt.z + v11.w * wt.w;

        unsigned short p0[4], p1[4];
#pragma unroll
        for (int e = 0; e < 4; e++) {
            __half a0, a1;
            h2split(o[e], a0, a1);
            p0[e] = __half_as_ushort(a0);
            p1[e] = __half_as_ushort(a1);
        }
        uint2 q0 = make_uint2((uint32_t)p0[0] | ((uint32_t)p0[1] << 16),
                              (uint32_t)p0[2] | ((uint32_t)p0[3] << 16));
        uint2 q1 = make_uint2((uint32_t)p1[0] | ((uint32_t)p1[1] << 16),
                              (uint32_t)p1[2] | ((uint32_t)p1[3] << 16));
        *(uint2*)(out0 + (size_t)pos * CDIM) = q0;
        *(uint2*)(out1 + (size_t)pos * CDIM) = q1;
    }
}

// ---- fused: split-K reduce + bias + tanh/softmax + deformable sampling ----
__global__ __launch_bounds__(256) void k_sample(const float* __restrict__ ref,
                                                const float* __restrict__ part,
                                                const float* __restrict__ bp,
                                                const float* __restrict__ bw,
                                                const float* __restrict__ value,
                                                __half* __restrict__ attA)
{
    int q = blockIdx.x;
    int n = q / LQ;
    int t = threadIdx.x;
    int h = t >> 5, d = t & 31;
    __shared__ float s_pw[NPW];
    __shared__ float s_w[NHEADS][16];
    __shared__ float s_ref[16];
    __shared__ int4  s_goff[NHEADS][16];
    __shared__ float4 s_gw[NHEADS][16];

    for (int j = t; j < NPW; j += 256) {
        float s = (j < 256) ? bp[j] : bw[j - 256];
        const float* p = part + (size_t)q * NPW + j;
#pragma unroll
        for (int z = 0; z < SPLITK; z++)
            s += p[(size_t)z * NQ * NPW];
        s_pw[j] = s;
    }
    if (t < 16) s_ref[t] = ref[(size_t)q * 16 + t];
    __syncthreads();

    if (t < 128) {
        const int HL[4] = {100, 50, 25, 13};
        const int WL[4] = {150, 75, 38, 19};
        const int SL[4] = {0, 15000, 18750, 19700};
        int hh = t >> 4, lp = t & 15, l = lp >> 2;
        float ox = tanhf(s_pw[2 * t]);
        float oy = tanhf(s_pw[2 * t + 1]);
        float pxn = s_ref[l * 4 + 0] + ox * s_ref[l * 4 + 2] * 0.5f;
        float pyn = s_ref[l * 4 + 1] + oy * s_ref[l * 4 + 3] * 0.5f;
        s_w[hh][lp] = s_pw[256 + t];

        float px = pxn * (float)WL[l] - 0.5f;
        float py = pyn * (float)HL[l] - 0.5f;
        float fy = floorf(py), fx = floorf(px);
        int y0 = (int)fy, x0 = (int)fx;
        float wy1 = py - fy, wx1 = px - fx;
        float wy0 = 1.f - wy1, wx0 = 1.f - wx1;
        bool ya = (y0 >= 0) && (y0 < HL[l]);
        bool yb = (y0 + 1 >= 0) && (y0 + 1 < HL[l]);
        bool xa = (x0 >= 0) && (x0 < WL[l]);
        bool xb = (x0 + 1 >= 0) && (x0 + 1 < WL[l]);
        int yc0 = min(max(y0, 0), HL[l] - 1);
        int yc1 = min(max(y0 + 1, 0), HL[l] - 1);
        int xc0 = min(max(x0, 0), WL[l] - 1);
        int xc1 = min(max(x0 + 1, 0), WL[l] - 1);
        int baseOff = (n * LEN_IN + SL[l]) * CDIM + hh * DH;
        s_goff[hh][lp] = make_int4(baseOff + (yc0 * WL[l] + xc0) * CDIM,
                                   baseOff + (yc0 * WL[l] + xc1) * CDIM,
                                   baseOff + (yc1 * WL[l] + xc0) * CDIM,
                                   baseOff + (yc1 * WL[l] + xc1) * CDIM);
        s_gw[hh][lp] = make_float4((ya && xa) ? wy0 * wx0 : 0.f,
                                   (ya && xb) ? wy0 * wx1 : 0.f,
                                   (yb && xa) ? wy1 * wx0 : 0.f,
                                   (yb && xb) ? wy1 * wx1 : 0.f);
    }
    __syncthreads();
    if (t < NHEADS) {
        float mx = -1e30f;
#pragma unroll
        for (int i = 0; i < 16; i++) mx = fmaxf(mx, s_w[t][i]);
        float sum = 0.f;
#pragma unroll
        for (int i = 0; i < 16; i++) {
            float e = expf(s_w[t][i] - mx);
            s_w[t][i] = e;
            sum += e;
        }
        float inv = 1.f / sum;
#pragma unroll
        for (int i = 0; i < 16; i++) s_w[t][i] *= inv;
    }
    __syncthreads();

    float acc = 0.f;
#pragma unroll
    for (int lp = 0; lp < 16; lp++) {
        const int4 off = s_goff[h][lp];
        const float4 gw = s_gw[h][lp];
        float v00 = value[off.x + d];
        float v01 = value[off.y + d];
        float v10 = value[off.z + d];
        float v11 = value[off.w + d];
        float inner = v00 * gw.x + v01 * gw.y + v10 * gw.z + v11 * gw.w;
        acc += s_w[h][lp] * inner;
    }
    __half h0, h1;
    h2split(acc, h0, h1);
    attA[(size_t)q * CDIM + t] = h0;
    attA[(size_t)NQPAD * CDIM + (size_t)q * CDIM + t] = h1;
}

// ------------------------------ launcher -----------------------------------
extern "C" void kernel_launch(void* const* d_in, const int* in_sizes, int n_in,
                              void* d_out, int out_size)
{
    (void)in_sizes; (void)n_in; (void)out_size;
    const float* ref  = (const float*)d_in[1];
    const float* flat = (const float*)d_in[2];
    const float* Wv   = (const float*)d_in[6];
    const float* bv   = (const float*)d_in[7];
    const float* Wp   = (const float*)d_in[8];
    const float* bp   = (const float*)d_in[9];
    const float* Ww   = (const float*)d_in[10];
    const float* bw   = (const float*)d_in[11];
    const float* Wo   = (const float*)d_in[12];
    const float* bo   = (const float*)d_in[13];
    float* out = (float*)d_out;

    float *p_value, *p_part;
    __half *p_roiA, *p_attA, *p_btv, *p_btpw, *p_btwo;
    cudaGetSymbolAddress((void**)&p_value, g_value);
    cudaGetSymbolAddress((void**)&p_roiA,  g_roiA);
    cudaGetSymbolAddress((void**)&p_attA,  g_attA);
    cudaGetSymbolAddress((void**)&p_part,  g_part);
    cudaGetSymbolAddress((void**)&p_btv,   g_btv);
    cudaGetSymbolAddress((void**)&p_btpw,  g_btpw);
    cudaGetSymbolAddress((void**)&p_btwo,  g_btwo);

    cudaFuncSetAttribute(mma_gemm, cudaFuncAttributeMaxDynamicSharedMemorySize,
                         SMEM_TOT);
    cudaFuncSetAttribute(mma_gemm_f32,
                         cudaFuncAttributeMaxDynamicSharedMemorySize, SMEM_TOT);

    // 0. all weight transposes + x64 scale + fp16 split (one launch)
    k_tsplit_all<<<dim3(12, ROI_DIM / 32, 2), 256>>>(
        Wp, Ww, p_btpw, Wv, p_btv, Wo, p_btwo);

    // 1. value = input_flatten @ Wv + bv  (A split fused; grid 2 x 624)
    mma_gemm_f32<<<dim3(CDIM / 128, (MV + 127) / 128, 1), 256, SMEM_TOT>>>(
        flat, CDIM,
        p_btv, (size_t)CDIM * CDIM, CDIM,
        p_value, CDIM, MV, CDIM, bv, WSCALE_INV);

    // 2. ROI align -> split fp16 roi planes
    k_roi<<<NQ, dim3(64, 8)>>>(ref, p_value, p_roiA);

    // 3. pw partials: roi @ [Wp | Ww]  (grid 3 x 10 x 28)
    mma_gemm<<<dim3(NPW / 128, NQPAD / 128, SPLITK), 256, SMEM_TOT>>>(
        p_roiA, (size_t)NQPAD * ROI_DIM, ROI_DIM,
        p_btpw, (size_t)NPW * ROI_DIM, ROI_DIM,
        p_part, NPW, (long long)NQ * NPW, NQ, KCHUNK, nullptr, WSCALE_INV);

    // 4. fused reduce + deformable sampling -> split fp16 att planes
    k_sample<<<NQ, 256>>>(ref, p_part, bp, bw, p_value, p_attA);

    // 5. out = att @ Wo + bo  (grid 2 x 10)
    mma_gemm<<<dim3(CDIM / 128, NQPAD / 128, 1), 256, SMEM_TOT>>>(
        p_attA, (size_t)NQPAD * CDIM, CDIM,
        p_btwo, (size_t)CDIM * CDIM, CDIM,
        out, CDIM, 0, NQ, CDIM, bo, WSCALE_INV);
}